// round 3
// baseline (speedup 1.0000x reference)
#include <cuda_runtime.h>
#include <cuda_bf16.h>
#include <cstdint>
#include <cstddef>

#define L_TOK 4096
#define KDIM  1024
#define G4H   4096
#define VOCAB 50257
#define VPAD  50432            // 197 * 256
#define NT2   197

// ---------------- scratch (__device__ globals; no allocation allowed) ---------
__device__ __nv_bfloat16 g_x[(size_t)L_TOK * KDIM];
__device__ __nv_bfloat16 g_Wih[(size_t)G4H * KDIM];
__device__ __nv_bfloat16 g_Wout[(size_t)VPAD * KDIM];
__device__ float         g_bias1[G4H];
__device__ float         g_bias2[VPAD];
__device__ __nv_bfloat16 g_gates_bf[(size_t)L_TOK * G4H];
__device__ __nv_bfloat16 g_h[(size_t)L_TOK * KDIM];
__device__ __nv_bfloat16 g_logits[(size_t)L_TOK * VPAD];
__device__ float         g_lse[L_TOK];

// ---------------- helpers -----------------------------------------------------
__device__ __forceinline__ uint32_t smem_u32(const void* p) {
    uint32_t a;
    asm("{ .reg .u64 t; cvta.to.shared.u64 t, %1; cvt.u32.u64 %0, t; }" : "=r"(a) : "l"(p));
    return a;
}
__device__ __forceinline__ uint32_t lds32(uint32_t a) {
    uint32_t v;
    asm volatile("ld.shared.b32 %0, [%1];" : "=r"(v) : "r"(a));
    return v;
}
__device__ __forceinline__ void mma16816(float* d, const uint32_t* a, const uint32_t* b) {
    asm volatile(
        "mma.sync.aligned.m16n8k16.row.col.f32.bf16.bf16.f32 "
        "{%0,%1,%2,%3},{%4,%5,%6,%7},{%8,%9},{%0,%1,%2,%3};"
        : "+f"(d[0]), "+f"(d[1]), "+f"(d[2]), "+f"(d[3])
        : "r"(a[0]), "r"(a[1]), "r"(a[2]), "r"(a[3]), "r"(b[0]), "r"(b[1]));
}

// ---------------- GEMM: C[M,N](bf16) = A[M,K] * B[N,K]^T + bias[N] -----------
// CTA tile 128x256, BK=32, 4-stage cp.async pipeline, 8 warps (64x64 each).
#define BM 128
#define BN 256
#define BK 32
#define STG 4
#define ROWB 80                                 // (32+8) bf16 per smem row
#define A_BYTES (BM * ROWB)                     // 10240
#define B_BYTES (BN * ROWB)                     // 20480
#define STAGE_BYTES (A_BYTES + B_BYTES)         // 30720
#define SMEM_BYTES (STG * STAGE_BYTES)          // 122880

__device__ __forceinline__ void stage_load(uint32_t sbase, int s,
                                           const __nv_bfloat16* A, const __nv_bfloat16* B,
                                           int m0, int n0, int k0, int tid) {
    uint32_t sa = sbase + s * STAGE_BYTES;
    uint32_t sb = sa + A_BYTES;
    // A: 128 rows x 4 chunks of 16B
    #pragma unroll
    for (int i = 0; i < 2; i++) {
        int c = tid + i * 256;
        int r = c >> 2, kc = (c & 3) * 8;
        const char* g = (const char*)(A + (size_t)(m0 + r) * KDIM + k0 + kc);
        asm volatile("cp.async.cg.shared.global [%0], [%1], 16;"
                     :: "r"(sa + r * ROWB + kc * 2), "l"(g) : "memory");
    }
    // B: 256 rows x 4 chunks of 16B
    #pragma unroll
    for (int i = 0; i < 4; i++) {
        int c = tid + i * 256;
        int r = c >> 2, kc = (c & 3) * 8;
        const char* g = (const char*)(B + (size_t)(n0 + r) * KDIM + k0 + kc);
        asm volatile("cp.async.cg.shared.global [%0], [%1], 16;"
                     :: "r"(sb + r * ROWB + kc * 2), "l"(g) : "memory");
    }
}

__global__ void __launch_bounds__(256, 1)
k_gemm(const __nv_bfloat16* __restrict__ A, const __nv_bfloat16* __restrict__ B,
       __nv_bfloat16* __restrict__ out, const float* __restrict__ bias, int ldOut) {
    extern __shared__ char smem[];
    uint32_t sbase = smem_u32(smem);
    int tid = threadIdx.x, wid = tid >> 5, lane = tid & 31;
    int g = lane >> 2, t = lane & 3;
    int m0 = blockIdx.y * BM, n0 = blockIdx.x * BN;
    int wm = (wid >> 2) * 64, wn = (wid & 3) * 64;

    float acc[4][8][4];
    #pragma unroll
    for (int i = 0; i < 4; i++)
        #pragma unroll
        for (int j = 0; j < 8; j++)
            #pragma unroll
            for (int q = 0; q < 4; q++) acc[i][j][q] = 0.0f;

    const int KT = KDIM / BK;   // 32
    // prologue: stages 0..2
    #pragma unroll
    for (int s = 0; s < STG - 1; s++) {
        stage_load(sbase, s, A, B, m0, n0, s * BK, tid);
        asm volatile("cp.async.commit_group;" ::: "memory");
    }

    for (int kt = 0; kt < KT; kt++) {
        int pf = kt + STG - 1;
        if (pf < KT) stage_load(sbase, pf & (STG - 1), A, B, m0, n0, pf * BK, tid);
        asm volatile("cp.async.commit_group;" ::: "memory");
        asm volatile("cp.async.wait_group %0;" :: "n"(STG - 1) : "memory");
        __syncthreads();

        uint32_t sa = sbase + (kt & (STG - 1)) * STAGE_BYTES;
        uint32_t sb = sa + A_BYTES;
        #pragma unroll
        for (int kk = 0; kk < 2; kk++) {
            int kb = kk * 32 + 4 * t;           // byte offset of k16 + 2t elems
            uint32_t aR[4][4], bR[8][2];
            #pragma unroll
            for (int i = 0; i < 4; i++) {
                uint32_t r0 = sa + (wm + 16 * i + g) * ROWB + kb;
                uint32_t r1 = r0 + 8 * ROWB;
                aR[i][0] = lds32(r0);
                aR[i][1] = lds32(r1);
                aR[i][2] = lds32(r0 + 16);
                aR[i][3] = lds32(r1 + 16);
            }
            #pragma unroll
            for (int j = 0; j < 8; j++) {
                uint32_t c0 = sb + (wn + 8 * j + g) * ROWB + kb;
                bR[j][0] = lds32(c0);
                bR[j][1] = lds32(c0 + 16);
            }
            #pragma unroll
            for (int i = 0; i < 4; i++)
                #pragma unroll
                for (int j = 0; j < 8; j++)
                    mma16816(acc[i][j], aR[i], bR[j]);
        }
        __syncthreads();
    }

    // epilogue: bf16 store with bias
    #pragma unroll
    for (int j = 0; j < 8; j++) {
        int col = n0 + wn + 8 * j + 2 * t;
        float b0 = bias[col], b1 = bias[col + 1];
        #pragma unroll
        for (int i = 0; i < 4; i++) {
            int row = m0 + wm + 16 * i + g;
            __nv_bfloat162 p0 = __float22bfloat162_rn(
                make_float2(acc[i][j][0] + b0, acc[i][j][1] + b1));
            __nv_bfloat162 p1 = __float22bfloat162_rn(
                make_float2(acc[i][j][2] + b0, acc[i][j][3] + b1));
            *reinterpret_cast<__nv_bfloat162*>(out + (size_t)row * ldOut + col) = p0;
            *reinterpret_cast<__nv_bfloat162*>(out + (size_t)(row + 8) * ldOut + col) = p1;
        }
    }
}

// ---------------- small kernels ----------------------------------------------
__global__ void k_bias(const float* __restrict__ b_ih, const float* __restrict__ b_hh,
                       const float* __restrict__ b_out) {
    int i = blockIdx.x * blockDim.x + threadIdx.x;
    if (i < G4H) g_bias1[i] = b_ih[i] + b_hh[i];
    if (i < VPAD) g_bias2[i] = (i < VOCAB) ? b_out[i] : -1e30f;
}

__global__ void k_prep_x(const int* __restrict__ sent, const float* __restrict__ emb) {
    int r = blockIdx.x;
    int tk = sent[r];
    const float* e = emb + (size_t)tk * KDIM;
    for (int j = threadIdx.x; j < KDIM; j += blockDim.x)
        g_x[(size_t)r * KDIM + j] = __float2bfloat16_rn(e[j]);
}

__global__ void k_convWih(const float* __restrict__ W) {
    int i = blockIdx.x * blockDim.x + threadIdx.x;
    if (i < G4H * KDIM) g_Wih[i] = __float2bfloat16_rn(W[i]);
}

__global__ void k_convWout(const float* __restrict__ W) {
    size_t n = (size_t)VPAD * KDIM;
    for (size_t i = (size_t)blockIdx.x * blockDim.x + threadIdx.x; i < n;
         i += (size_t)gridDim.x * blockDim.x) {
        size_t r = i >> 10;
        g_Wout[i] = (r < VOCAB) ? __float2bfloat16_rn(W[i]) : __float2bfloat16_rn(0.0f);
    }
}

__global__ void k_act() {
    int idx = blockIdx.x * blockDim.x + threadIdx.x;
    if (idx >= L_TOK * KDIM) return;
    int r = idx >> 10, j = idx & 1023;
    const __nv_bfloat16* gr = g_gates_bf + (size_t)r * G4H;
    float gi = __bfloat162float(gr[j]);
    float gg = __bfloat162float(gr[2048 + j]);
    float go = __bfloat162float(gr[3072 + j]);
    float si = 1.0f / (1.0f + __expf(-gi));
    float so = 1.0f / (1.0f + __expf(-go));
    float c  = si * tanhf(gg);
    float h  = so * tanhf(c);
    g_h[(size_t)r * KDIM + j] = __float2bfloat16_rn(h);
}

// logits are bounded (|x| << 1), pads carry -1e30 -> exp = 0: no max pass needed.
__global__ void k_lse() {
    int row = blockIdx.x;
    const uint4* lg = reinterpret_cast<const uint4*>(g_logits + (size_t)row * VPAD);
    float s = 0.0f;
    for (int i = threadIdx.x; i < VPAD / 8; i += blockDim.x) {
        uint4 v = lg[i];
        uint32_t w[4] = {v.x, v.y, v.z, v.w};
        #pragma unroll
        for (int q = 0; q < 4; q++) {
            __nv_bfloat162 p = *reinterpret_cast<__nv_bfloat162*>(&w[q]);
            float2 f = __bfloat1622float2(p);
            s += __expf(f.x) + __expf(f.y);
        }
    }
    #pragma unroll
    for (int o = 16; o > 0; o >>= 1) s += __shfl_xor_sync(0xFFFFFFFFu, s, o);
    __shared__ float ws[8];
    if ((threadIdx.x & 31) == 0) ws[threadIdx.x >> 5] = s;
    __syncthreads();
    if (threadIdx.x == 0) {
        float tt = 0.0f;
        #pragma unroll
        for (int q = 0; q < 8; q++) tt += ws[q];
        g_lse[row] = logf(tt);
    }
}

__global__ void k_final(float* __restrict__ out) {
    int row  = blockIdx.y;
    int colb = (blockIdx.x * blockDim.x + threadIdx.x) * 8;
    if (colb >= VPAD) return;
    uint4 v = reinterpret_cast<const uint4*>(g_logits + (size_t)row * VPAD)[colb >> 3];
    float l = g_lse[row];
    float* orow = out + (size_t)row * VOCAB;
    uint32_t w[4] = {v.x, v.y, v.z, v.w};
    #pragma unroll
    for (int q = 0; q < 4; q++) {
        __nv_bfloat162 p = *reinterpret_cast<__nv_bfloat162*>(&w[q]);
        float2 f = __bfloat1622float2(p);
        int c0 = colb + 2 * q;
        if (c0 < VOCAB)     orow[c0]     = f.x - l;
        if (c0 + 1 < VOCAB) orow[c0 + 1] = f.y - l;
    }
}

// ---------------- launch ------------------------------------------------------
extern "C" void kernel_launch(void* const* d_in, const int* in_sizes, int n_in,
                              void* d_out, int out_size) {
    // input order hedge: dict order (sentence first) vs signature order (emb first)
    int i_sent, i_emb, i_Wih, i_bih, i_bhh, i_Wout, i_bout;
    if (in_sizes[0] == L_TOK) {  // dict order: sentence, emb, W_ih, W_hh, b_ih, b_hh, W_out, b_out
        i_sent = 0; i_emb = 1; i_Wih = 2; i_bih = 4; i_bhh = 5; i_Wout = 6; i_bout = 7;
    } else {                     // signature order: emb, W_ih, W_hh, b_ih, b_hh, W_out, b_out, sentence
        i_emb = 0; i_Wih = 1; i_bih = 3; i_bhh = 4; i_Wout = 5; i_bout = 6; i_sent = 7;
    }
    const int*   sent = (const int*)  d_in[i_sent];
    const float* emb  = (const float*)d_in[i_emb];
    const float* Wih  = (const float*)d_in[i_Wih];
    const float* bih  = (const float*)d_in[i_bih];
    const float* bhh  = (const float*)d_in[i_bhh];
    const float* Wout = (const float*)d_in[i_Wout];
    const float* bout = (const float*)d_in[i_bout];
    float* out = (float*)d_out;

    cudaFuncSetAttribute((const void*)k_gemm,
                         cudaFuncAttributeMaxDynamicSharedMemorySize, SMEM_BYTES);

    __nv_bfloat16 *px, *pwih, *pwout, *pgates, *ph, *plog;
    float *pb1, *pb2;
    cudaGetSymbolAddress((void**)&px, g_x);
    cudaGetSymbolAddress((void**)&pwih, g_Wih);
    cudaGetSymbolAddress((void**)&pwout, g_Wout);
    cudaGetSymbolAddress((void**)&pgates, g_gates_bf);
    cudaGetSymbolAddress((void**)&ph, g_h);
    cudaGetSymbolAddress((void**)&plog, g_logits);
    cudaGetSymbolAddress((void**)&pb1, g_bias1);
    cudaGetSymbolAddress((void**)&pb2, g_bias2);

    k_bias<<<(VPAD + 255) / 256, 256>>>(bih, bhh, bout);
    k_prep_x<<<L_TOK, 256>>>(sent, emb);
    k_convWih<<<(G4H * KDIM + 255) / 256, 256>>>(Wih);
    k_convWout<<<8192, 256>>>(Wout);

    // gates = x @ W_ih^T + (b_ih + b_hh)
    k_gemm<<<dim3(G4H / BN, L_TOK / BM), 256, SMEM_BYTES>>>(px, pwih, pgates, pb1, G4H);
    k_act<<<(L_TOK * KDIM + 255) / 256, 256>>>();
    // logits = h @ W_out^T + b_out  (pads get -1e30)
    k_gemm<<<dim3(NT2, L_TOK / BM), 256, SMEM_BYTES>>>(ph, pwout, plog, pb2, VPAD);

    k_lse<<<L_TOK, 256>>>();
    k_final<<<dim3((VPAD / 8 + 255) / 256, L_TOK), 256>>>(out);
    (void)n_in; (void)out_size;
}

// round 4
// speedup vs baseline: 1.0045x; 1.0045x over previous
#include <cuda_runtime.h>
#include <cuda_bf16.h>
#include <cstdint>
#include <cstddef>

#define L_TOK 4096
#define KDIM  1024
#define NPACK 3072             // i,g,o gates only (f is dead: c0=0)
#define VOCAB 50257
#define VPAD  50432            // 197 * 256
#define NT2   197

// ---------------- scratch (__device__ globals; no allocation allowed) ---------
__device__ __nv_bfloat16 g_x[(size_t)L_TOK * KDIM];
__device__ __nv_bfloat16 g_Wih[(size_t)NPACK * KDIM];
__device__ __nv_bfloat16 g_Wout[(size_t)VPAD * KDIM];
__device__ float         g_bias1[NPACK];
__device__ float         g_bias2[VPAD];
__device__ __nv_bfloat16 g_gates_bf[(size_t)L_TOK * NPACK];
__device__ __nv_bfloat16 g_h[(size_t)L_TOK * KDIM];
__device__ __nv_bfloat16 g_logits[(size_t)L_TOK * VPAD];
__device__ float         g_psum[(size_t)L_TOK * 1024];   // per-(row, n-warp-tile) exp sums
__device__ float         g_lse[L_TOK];

// ---------------- helpers -----------------------------------------------------
__device__ __forceinline__ uint32_t smem_u32(const void* p) {
    uint32_t a;
    asm("{ .reg .u64 t; cvta.to.shared.u64 t, %1; cvt.u32.u64 %0, t; }" : "=r"(a) : "l"(p));
    return a;
}
__device__ __forceinline__ void ldsm_x4(uint32_t* r, uint32_t addr) {
    asm volatile("ldmatrix.sync.aligned.m8n8.x4.shared.b16 {%0,%1,%2,%3}, [%4];"
                 : "=r"(r[0]), "=r"(r[1]), "=r"(r[2]), "=r"(r[3]) : "r"(addr));
}
__device__ __forceinline__ void mma16816(float* d, const uint32_t* a, const uint32_t* b) {
    asm volatile(
        "mma.sync.aligned.m16n8k16.row.col.f32.bf16.bf16.f32 "
        "{%0,%1,%2,%3},{%4,%5,%6,%7},{%8,%9},{%0,%1,%2,%3};"
        : "+f"(d[0]), "+f"(d[1]), "+f"(d[2]), "+f"(d[3])
        : "r"(a[0]), "r"(a[1]), "r"(a[2]), "r"(a[3]), "r"(b[0]), "r"(b[1]));
}

// ---------------- GEMM: C[M,N](bf16) = A[M,K] * B[N,K]^T + bias[N] -----------
// CTA tile 128x256, BK=32, 4-stage cp.async pipeline, 8 warps (64x64 each),
// ldmatrix fragment loads. blockIdx.x = m-tile (fast) for L2-friendly B reuse.
#define BM 128
#define BN 256
#define BK 32
#define STG 4
#define ROWB 80                                 // (32+8) bf16 per smem row
#define A_BYTES (BM * ROWB)                     // 10240
#define B_BYTES (BN * ROWB)                     // 20480
#define STAGE_BYTES (A_BYTES + B_BYTES)         // 30720
#define SMEM_BYTES (STG * STAGE_BYTES)          // 122880

__device__ __forceinline__ void stage_load(uint32_t sbase, int s,
                                           const __nv_bfloat16* A, const __nv_bfloat16* B,
                                           int m0, int n0, int k0, int tid) {
    uint32_t sa = sbase + s * STAGE_BYTES;
    uint32_t sb = sa + A_BYTES;
    #pragma unroll
    for (int i = 0; i < 2; i++) {
        int c = tid + i * 256;
        int r = c >> 2, kc = (c & 3) * 16;      // byte offset within 64B row
        const char* g = (const char*)(A + (size_t)(m0 + r) * KDIM + k0) + kc;
        asm volatile("cp.async.cg.shared.global [%0], [%1], 16;"
                     :: "r"(sa + r * ROWB + kc), "l"(g) : "memory");
    }
    #pragma unroll
    for (int i = 0; i < 4; i++) {
        int c = tid + i * 256;
        int r = c >> 2, kc = (c & 3) * 16;
        const char* g = (const char*)(B + (size_t)(n0 + r) * KDIM + k0) + kc;
        asm volatile("cp.async.cg.shared.global [%0], [%1], 16;"
                     :: "r"(sb + r * ROWB + kc), "l"(g) : "memory");
    }
}

__global__ void __launch_bounds__(256, 1)
k_gemm(const __nv_bfloat16* __restrict__ A, const __nv_bfloat16* __restrict__ B,
       __nv_bfloat16* __restrict__ out, const float* __restrict__ bias, int ldOut,
       float* __restrict__ psum) {
    extern __shared__ char smem[];
    uint32_t sbase = smem_u32(smem);
    int tid = threadIdx.x, wid = tid >> 5, lane = tid & 31;
    int g = lane >> 2, t = lane & 3;
    int m0 = blockIdx.x * BM, n0 = blockIdx.y * BN;
    int wm = (wid >> 2) * 64, wn = (wid & 3) * 64;

    float acc[4][8][4];
    #pragma unroll
    for (int i = 0; i < 4; i++)
        #pragma unroll
        for (int j = 0; j < 8; j++)
            #pragma unroll
            for (int q = 0; q < 4; q++) acc[i][j][q] = 0.0f;

    const int KT = KDIM / BK;   // 32
    #pragma unroll
    for (int s = 0; s < STG - 1; s++) {
        stage_load(sbase, s, A, B, m0, n0, s * BK, tid);
        asm volatile("cp.async.commit_group;" ::: "memory");
    }

    // ldmatrix lane-address components (per thread, loop-invariant)
    int a_row = (lane & 15);                 // rows 0..15 of the 16x16 A tile
    int a_off = (lane >> 4) * 16;            // k half (bytes)
    int b_row = (lane & 7) + (lane >> 4) * 8;  // n row within 16-row j-pair
    int b_off = ((lane >> 3) & 1) * 16;      // k half (bytes)

    for (int kt = 0; kt < KT; kt++) {
        int pf = kt + STG - 1;
        if (pf < KT) stage_load(sbase, pf & (STG - 1), A, B, m0, n0, pf * BK, tid);
        asm volatile("cp.async.commit_group;" ::: "memory");
        asm volatile("cp.async.wait_group %0;" :: "n"(STG - 1) : "memory");
        __syncthreads();

        uint32_t sa = sbase + (kt & (STG - 1)) * STAGE_BYTES;
        uint32_t sb = sa + A_BYTES;
        #pragma unroll
        for (int kk = 0; kk < 2; kk++) {
            int kb = kk * 32;
            uint32_t aR[4][4], bR[8][2];
            #pragma unroll
            for (int i = 0; i < 4; i++)
                ldsm_x4(aR[i], sa + (wm + 16 * i + a_row) * ROWB + kb + a_off);
            #pragma unroll
            for (int jp = 0; jp < 4; jp++) {
                uint32_t r4[4];
                ldsm_x4(r4, sb + (wn + 16 * jp + b_row) * ROWB + kb + b_off);
                bR[2 * jp][0] = r4[0]; bR[2 * jp][1] = r4[1];
                bR[2 * jp + 1][0] = r4[2]; bR[2 * jp + 1][1] = r4[3];
            }
            #pragma unroll
            for (int i = 0; i < 4; i++)
                #pragma unroll
                for (int j = 0; j < 8; j++)
                    mma16816(acc[i][j], aR[i], bR[j]);
        }
        __syncthreads();
    }

    // epilogue: bf16 store with bias (+ optional per-row exp partial sums)
    float rsum[4][2];
    #pragma unroll
    for (int i = 0; i < 4; i++) { rsum[i][0] = 0.0f; rsum[i][1] = 0.0f; }

    #pragma unroll
    for (int j = 0; j < 8; j++) {
        int col = n0 + wn + 8 * j + 2 * t;
        float b0 = bias[col], b1 = bias[col + 1];
        #pragma unroll
        for (int i = 0; i < 4; i++) {
            int row = m0 + wm + 16 * i + g;
            float f0 = acc[i][j][0] + b0, f1 = acc[i][j][1] + b1;
            float f2 = acc[i][j][2] + b0, f3 = acc[i][j][3] + b1;
            __nv_bfloat162 p0 = __float22bfloat162_rn(make_float2(f0, f1));
            __nv_bfloat162 p1 = __float22bfloat162_rn(make_float2(f2, f3));
            *reinterpret_cast<__nv_bfloat162*>(out + (size_t)row * ldOut + col) = p0;
            *reinterpret_cast<__nv_bfloat162*>(out + (size_t)(row + 8) * ldOut + col) = p1;
            if (psum) {
                rsum[i][0] += __expf(f0) + __expf(f1);
                rsum[i][1] += __expf(f2) + __expf(f3);
            }
        }
    }
    if (psum) {
        int slot = blockIdx.y * 4 + (wid & 3);
        #pragma unroll
        for (int i = 0; i < 4; i++)
            #pragma unroll
            for (int h = 0; h < 2; h++) {
                float s = rsum[i][h];
                s += __shfl_xor_sync(0xFFFFFFFFu, s, 1);
                s += __shfl_xor_sync(0xFFFFFFFFu, s, 2);
                if (t == 0) {
                    int row = m0 + wm + 16 * i + 8 * h + g;
                    psum[((size_t)row << 10) + slot] = s;
                }
            }
    }
}

// ---------------- small kernels ----------------------------------------------
__global__ void k_bias(const float* __restrict__ b_ih, const float* __restrict__ b_hh,
                       const float* __restrict__ b_out) {
    int i = blockIdx.x * blockDim.x + threadIdx.x;
    if (i < NPACK) {
        int src = (i < 1024) ? i : i + 1024;     // skip f-gate rows [1024,2048)
        g_bias1[i] = b_ih[src] + b_hh[src];
    }
    if (i < VPAD) g_bias2[i] = (i < VOCAB) ? b_out[i] : -1e30f;
}

__global__ void k_prep_x(const int* __restrict__ sent, const float* __restrict__ emb) {
    int r = blockIdx.x;
    int tk = sent[r];
    const float* e = emb + (size_t)tk * KDIM;
    for (int j = threadIdx.x; j < KDIM; j += blockDim.x)
        g_x[(size_t)r * KDIM + j] = __float2bfloat16_rn(e[j]);
}

__global__ void k_convWih(const float* __restrict__ W) {
    int i = blockIdx.x * blockDim.x + threadIdx.x;
    if (i >= NPACK * KDIM) return;
    int r = i >> 10, c = i & 1023;
    int src = (r < 1024) ? r : r + 1024;
    g_Wih[i] = __float2bfloat16_rn(W[(size_t)src * KDIM + c]);
}

__global__ void k_convWout(const float* __restrict__ W) {
    size_t n = (size_t)VPAD * KDIM;
    for (size_t i = (size_t)blockIdx.x * blockDim.x + threadIdx.x; i < n;
         i += (size_t)gridDim.x * blockDim.x) {
        size_t r = i >> 10;
        g_Wout[i] = (r < VOCAB) ? __float2bfloat16_rn(W[i]) : __float2bfloat16_rn(0.0f);
    }
}

__global__ void k_act() {
    int idx = blockIdx.x * blockDim.x + threadIdx.x;
    if (idx >= L_TOK * KDIM) return;
    int r = idx >> 10, j = idx & 1023;
    const __nv_bfloat16* gr = g_gates_bf + (size_t)r * NPACK;
    float gi = __bfloat162float(gr[j]);
    float gg = __bfloat162float(gr[1024 + j]);
    float go = __bfloat162float(gr[2048 + j]);
    float si = 1.0f / (1.0f + __expf(-gi));
    float so = 1.0f / (1.0f + __expf(-go));
    float c  = si * tanhf(gg);
    float h  = so * tanhf(c);
    g_h[(size_t)r * KDIM + j] = __float2bfloat16_rn(h);
}

// reduce per-warp exp partials (788 per row) -> lse
__global__ void k_lse() {
    int row = blockIdx.x * 8 + (threadIdx.x >> 5);
    int lane = threadIdx.x & 31;
    const float* p = g_psum + ((size_t)row << 10);
    float s = 0.0f;
    for (int i = lane; i < NT2 * 4; i += 32) s += p[i];
    #pragma unroll
    for (int o = 16; o > 0; o >>= 1) s += __shfl_xor_sync(0xFFFFFFFFu, s, o);
    if (lane == 0) g_lse[row] = logf(s);
}

__global__ void k_final(float* __restrict__ out) {
    int row  = blockIdx.y;
    int colb = (blockIdx.x * blockDim.x + threadIdx.x) * 8;
    if (colb >= VPAD) return;
    uint4 v = reinterpret_cast<const uint4*>(g_logits + (size_t)row * VPAD)[colb >> 3];
    float l = g_lse[row];
    float* orow = out + (size_t)row * VOCAB;
    uint32_t w[4] = {v.x, v.y, v.z, v.w};
    #pragma unroll
    for (int q = 0; q < 4; q++) {
        __nv_bfloat162 p = *reinterpret_cast<__nv_bfloat162*>(&w[q]);
        float2 f = __bfloat1622float2(p);
        int c0 = colb + 2 * q;
        if (c0 < VOCAB)     orow[c0]     = f.x - l;
        if (c0 + 1 < VOCAB) orow[c0 + 1] = f.y - l;
    }
}

// ---------------- launch ------------------------------------------------------
extern "C" void kernel_launch(void* const* d_in, const int* in_sizes, int n_in,
                              void* d_out, int out_size) {
    int i_sent, i_emb, i_Wih, i_bih, i_bhh, i_Wout, i_bout;
    if (in_sizes[0] == L_TOK) {  // dict order
        i_sent = 0; i_emb = 1; i_Wih = 2; i_bih = 4; i_bhh = 5; i_Wout = 6; i_bout = 7;
    } else {                     // signature order
        i_emb = 0; i_Wih = 1; i_bih = 3; i_bhh = 4; i_Wout = 5; i_bout = 6; i_sent = 7;
    }
    const int*   sent = (const int*)  d_in[i_sent];
    const float* emb  = (const float*)d_in[i_emb];
    const float* Wih  = (const float*)d_in[i_Wih];
    const float* bih  = (const float*)d_in[i_bih];
    const float* bhh  = (const float*)d_in[i_bhh];
    const float* Wout = (const float*)d_in[i_Wout];
    const float* bout = (const float*)d_in[i_bout];
    float* out = (float*)d_out;

    cudaFuncSetAttribute((const void*)k_gemm,
                         cudaFuncAttributeMaxDynamicSharedMemorySize, SMEM_BYTES);

    __nv_bfloat16 *px, *pwih, *pwout, *pgates, *ph, *plog;
    float *pb1, *pb2, *pps;
    cudaGetSymbolAddress((void**)&px, g_x);
    cudaGetSymbolAddress((void**)&pwih, g_Wih);
    cudaGetSymbolAddress((void**)&pwout, g_Wout);
    cudaGetSymbolAddress((void**)&pgates, g_gates_bf);
    cudaGetSymbolAddress((void**)&ph, g_h);
    cudaGetSymbolAddress((void**)&plog, g_logits);
    cudaGetSymbolAddress((void**)&pb1, g_bias1);
    cudaGetSymbolAddress((void**)&pb2, g_bias2);
    cudaGetSymbolAddress((void**)&pps, g_psum);

    k_bias<<<(VPAD + 255) / 256, 256>>>(bih, bhh, bout);
    k_prep_x<<<L_TOK, 256>>>(sent, emb);
    k_convWih<<<(NPACK * KDIM + 255) / 256, 256>>>(Wih);
    k_convWout<<<8192, 256>>>(Wout);

    // gates(packed) = x @ W_ih_packed^T + bias1
    k_gemm<<<dim3(L_TOK / BM, NPACK / BN), 256, SMEM_BYTES>>>(px, pwih, pgates, pb1, NPACK, nullptr);
    k_act<<<(L_TOK * KDIM + 255) / 256, 256>>>();
    // logits = h @ W_out^T + b_out (pads -1e30); fused exp partial sums
    k_gemm<<<dim3(L_TOK / BM, NT2), 256, SMEM_BYTES>>>(ph, pwout, plog, pb2, VPAD, pps);

    k_lse<<<L_TOK / 8, 256>>>();
    k_final<<<dim3((VPAD / 8 + 255) / 256, L_TOK), 256>>>(out);
    (void)n_in; (void)out_size;
}